// round 3
// baseline (speedup 1.0000x reference)
#include <cuda_runtime.h>

// ---------------------------------------------------------------------------
// Problem constants
// ---------------------------------------------------------------------------
#define BSZ    64
#define TLEN   512
#define UDIM   1024
#define OMEGA_F 0.006135923151542565f   // 2*pi/1024

// Chunked-scan parameters: 8 chunks of 64 steps, 32-step zero-state warmup.
// Truncation error per chunk start ~ ||(0.5A)^32|| ~ 2^-32 (A is Ginibre-scaled).
#define OV      32
#define CHUNKS  8
#define CLEN    64                 // TLEN / CHUNKS
#define NSTEP   (CLEN + OV)        // 96
#define SROWS   (CHUNKS * BSZ)     // 512
#define NCTA_SCAN 128

// ---------------------------------------------------------------------------
// Device scratch (static __device__ arrays; no runtime allocation)
// ---------------------------------------------------------------------------
// W[slot][b][u], slot = t + OV.  slots [0,OV-1]: zero pad except slot OV-1 = z0
// (injecting z0 as the input at t=-1 makes chunk 0 exact: z_0 = M*0 + z0).
__device__ float2     g_W[(size_t)(TLEN + OV) * BSZ * UDIM];
// Packed complex matrices for f32x2 FMA: per (k,n): lo=(re,im), hi=(-im,re),
// both scaled by 0.5.
__device__ ulonglong2 g_Ap[(size_t)UDIM * UDIM];
__device__ ulonglong2 g_Bp[(size_t)UDIM * UDIM];
// Scan state double buffer [512 rows = 8 chunks x 64 batch][1024]
__device__ float2     g_zst[2][SROWS * UDIM];
// Grid barrier state (zero-initialized at module load; phase monotone across replays)
__device__ unsigned   g_bar_cnt;
__device__ unsigned   g_bar_phase;

// ---------------------------------------------------------------------------
// Packed f32x2 helpers
// ---------------------------------------------------------------------------
static __device__ __forceinline__ unsigned long long pk2(float a, float b) {
    unsigned long long r;
    asm("mov.b64 %0, {%1, %2};" : "=l"(r) : "f"(a), "f"(b));
    return r;
}
static __device__ __forceinline__ void upk2(unsigned long long v, float& a, float& b) {
    asm("mov.b64 {%0, %1}, %2;" : "=f"(a), "=f"(b) : "l"(v));
}
static __device__ __forceinline__ unsigned long long ffma2(
    unsigned long long a, unsigned long long b, unsigned long long c) {
    unsigned long long d;
    asm("fma.rn.f32x2 %0, %1, %2, %3;" : "=l"(d) : "l"(a), "l"(b), "l"(c));
    return d;
}

// ---------------------------------------------------------------------------
// Kernel 0: pack A and B into f32x2-friendly layout, init W pad + z state
// ---------------------------------------------------------------------------
__global__ __launch_bounds__(256) void pack_kernel(
    const float* __restrict__ Ar, const float* __restrict__ Ai,
    const float* __restrict__ Br, const float* __restrict__ Bi,
    const float* __restrict__ z0r, const float* __restrict__ z0i)
{
    int i = blockIdx.x * 256 + threadIdx.x;
    if (i < UDIM * UDIM) {
        float ar = 0.5f * Ar[i], ai = 0.5f * Ai[i];
        ulonglong2 pa; pa.x = pk2(ar, ai); pa.y = pk2(-ai, ar);
        g_Ap[i] = pa;
        float br = 0.5f * Br[i], bi = 0.5f * Bi[i];
        ulonglong2 pb; pb.x = pk2(br, bi); pb.y = pk2(-bi, br);
        g_Bp[i] = pb;
    }
    if (i < OV * BSZ * UDIM) {   // 2,097,152 — largest task, sizes the grid
        int slot = i >> 16;      // / (BSZ*UDIM)
        int r    = i & 65535;
        g_W[i] = (slot == OV - 1) ? make_float2(z0r[r], z0i[r])
                                  : make_float2(0.f, 0.f);
    }
    if (i < SROWS * UDIM) g_zst[0][i] = make_float2(0.f, 0.f);
}

// ---------------------------------------------------------------------------
// Kernel 1: W[t][b][:] = 0.5 * (x[b][t][:] @ Bw)   (written to slot t+OV)
//   rows m = b*TLEN + t (x is [B,T,U] row-major), M=32768, N=1024, K=1024
//   CTA tile 128x64, 256 threads, 8x4 complex micro-tile, f32x2 FMA
// ---------------------------------------------------------------------------
__global__ __launch_bounds__(256) void wgemm_kernel(
    const float* __restrict__ xr, const float* __restrict__ xi)
{
    __shared__ float2     Xs[16][129];
    __shared__ ulonglong2 Bs[16][64];

    int m0  = blockIdx.y * 128;
    int n0  = blockIdx.x * 64;
    int tid = threadIdx.x;
    int tx  = tid & 15;    // col group: col = tx + 16*j
    int ty  = tid >> 4;    // row group: row = ty + 16*i

    unsigned long long acc[8][4];
    #pragma unroll
    for (int i = 0; i < 8; i++)
        #pragma unroll
        for (int j = 0; j < 4; j++) acc[i][j] = 0ull;

    for (int k0 = 0; k0 < UDIM; k0 += 16) {
        // X tile 128x16 (8 per thread), k-coalesced
        #pragma unroll
        for (int l = 0; l < 8; l++) {
            int idx = tid + l * 256;
            int mm = idx >> 4, kk = idx & 15;
            size_t g = (size_t)(m0 + mm) * UDIM + (k0 + kk);
            Xs[kk][mm] = make_float2(xr[g], xi[g]);
        }
        // B tile 16x64 (4 per thread), n-coalesced
        #pragma unroll
        for (int l = 0; l < 4; l++) {
            int idx = tid + l * 256;
            int kk = idx >> 6, nn = idx & 63;
            Bs[kk][nn] = g_Bp[(size_t)(k0 + kk) * UDIM + (n0 + nn)];
        }
        __syncthreads();

        #pragma unroll
        for (int kk = 0; kk < 16; kk++) {
            ulonglong2 bv[4];
            unsigned long long zrr[8], zii[8];
            #pragma unroll
            for (int j = 0; j < 4; j++) bv[j] = Bs[kk][tx + 16 * j];
            #pragma unroll
            for (int i = 0; i < 8; i++) {
                float2 z = Xs[kk][ty + 16 * i];
                zrr[i] = pk2(z.x, z.x);
                zii[i] = pk2(z.y, z.y);
            }
            #pragma unroll
            for (int i = 0; i < 8; i++)
                #pragma unroll
                for (int j = 0; j < 4; j++) {
                    acc[i][j] = ffma2(zrr[i], bv[j].x, acc[i][j]);
                    acc[i][j] = ffma2(zii[i], bv[j].y, acc[i][j]);
                }
        }
        __syncthreads();
    }

    #pragma unroll
    for (int i = 0; i < 8; i++) {
        int m = m0 + ty + 16 * i;
        int b = m >> 9;             // m / TLEN
        int t = m & (TLEN - 1);     // m % TLEN
        size_t base = ((size_t)(t + OV) * BSZ + b) * UDIM + n0 + tx;
        #pragma unroll
        for (int j = 0; j < 4; j++) {
            float re, im; upk2(acc[i][j], re, im);
            g_W[base + 16 * j] = make_float2(re, im);
        }
    }
}

// ---------------------------------------------------------------------------
// Grid barrier (all 128 CTAs co-resident: 128 < 148 SMs, one wave)
// ---------------------------------------------------------------------------
static __device__ __forceinline__ void grid_barrier()
{
    __threadfence();
    __syncthreads();
    if (threadIdx.x == 0) {
        unsigned my = *(volatile unsigned*)&g_bar_phase;
        unsigned rank = atomicAdd(&g_bar_cnt, 1u);
        if (rank == NCTA_SCAN - 1) {
            g_bar_cnt = 0;
            __threadfence();
            *(volatile unsigned*)&g_bar_phase = my + 1u;
        } else {
            while (*(volatile unsigned*)&g_bar_phase == my) __nanosleep(32);
        }
        __threadfence();
    }
    __syncthreads();
}

// ---------------------------------------------------------------------------
// Kernel 2: persistent chunked scan.
//   96 steps; per step: Znew = Zold @ M + W_t  (512x1024x1024 complex GEMM),
//   Hopf activation + output write for steps past warmup. Grid barrier between
//   steps. CTA tile 64 rows x 64 cols, 128 threads, 4x8 micro, f32x2 FMA.
// ---------------------------------------------------------------------------
__global__ __launch_bounds__(128) void scan_kernel(float2* __restrict__ out)
{
    __shared__ float2     Zs[16][65];
    __shared__ ulonglong2 As[16][64];

    int c   = blockIdx.x >> 4;          // chunk 0..7
    int n0  = (blockIdx.x & 15) << 6;   // col tile
    int tid = threadIdx.x;
    int tx  = tid & 7;                  // col group: col = tx + 8*j
    int ty  = tid >> 3;                 // row group: row = ty + 16*i (ty 0..15)

    for (int s = 0; s < NSTEP; s++) {
        const float2* __restrict__ cur = g_zst[s & 1];
        float2*       __restrict__ nxt = g_zst[(s + 1) & 1];

        unsigned long long acc[4][8];
        #pragma unroll
        for (int i = 0; i < 4; i++)
            #pragma unroll
            for (int j = 0; j < 8; j++) acc[i][j] = 0ull;

        for (int k0 = 0; k0 < UDIM; k0 += 16) {
            // Z tile 64x16 (8 per thread)
            #pragma unroll
            for (int l = 0; l < 8; l++) {
                int idx = tid + l * 128;
                int mm = idx >> 4, kk = idx & 15;
                Zs[kk][mm] = cur[(size_t)(c * BSZ + mm) * UDIM + (k0 + kk)];
            }
            // A tile 16x64 (8 per thread)
            #pragma unroll
            for (int l = 0; l < 8; l++) {
                int idx = tid + l * 128;
                int kk = idx >> 6, nn = idx & 63;
                As[kk][nn] = g_Ap[(size_t)(k0 + kk) * UDIM + (n0 + nn)];
            }
            __syncthreads();

            #pragma unroll
            for (int kk = 0; kk < 16; kk++) {
                ulonglong2 av[8];
                unsigned long long zrr[4], zii[4];
                #pragma unroll
                for (int j = 0; j < 8; j++) av[j] = As[kk][tx + 8 * j];
                #pragma unroll
                for (int i = 0; i < 4; i++) {
                    float2 z = Zs[kk][ty + 16 * i];
                    zrr[i] = pk2(z.x, z.x);
                    zii[i] = pk2(z.y, z.y);
                }
                #pragma unroll
                for (int i = 0; i < 4; i++)
                    #pragma unroll
                    for (int j = 0; j < 8; j++) {
                        acc[i][j] = ffma2(zrr[i], av[j].x, acc[i][j]);
                        acc[i][j] = ffma2(zii[i], av[j].y, acc[i][j]);
                    }
            }
            __syncthreads();
        }

        int wslot = c * CLEN + s;        // = (t of this step) + OV
        int tout  = c * CLEN + s - OV;   // output timestep (valid when s >= OV)
        #pragma unroll
        for (int i = 0; i < 4; i++) {
            int b = ty + 16 * i;
            size_t wbase = ((size_t)wslot * BSZ + b) * UDIM + n0 + tx;
            size_t zbase = ((size_t)(c * BSZ + b)) * (size_t)UDIM + n0 + tx;
            #pragma unroll
            for (int j = 0; j < 8; j++) {
                float re, im; upk2(acc[i][j], re, im);
                float2 w = g_W[wbase + 8 * j];
                float zr = re + w.x;
                float zi = im + w.y;
                nxt[zbase + 8 * j] = make_float2(zr, zi);
                if (s >= OV) {
                    // y = z_i * ((2 - |z_i|^2) + i*omega)
                    float r2 = zr * zr + zi * zi;
                    float cc = 2.0f - r2;
                    float yr = fmaf(-OMEGA_F, zi, cc * zr);
                    float yi = fmaf( OMEGA_F, zr, cc * zi);
                    out[((size_t)b * TLEN + tout) * UDIM + n0 + tx + 8 * j] =
                        make_float2(yr, yi);
                }
            }
        }
        grid_barrier();
    }
}

// ---------------------------------------------------------------------------
// Launch: 3 graph nodes total
// ---------------------------------------------------------------------------
extern "C" void kernel_launch(void* const* d_in, const int* in_sizes, int n_in,
                              void* d_out, int out_size)
{
    const float* xr  = (const float*)d_in[0];
    const float* xi  = (const float*)d_in[1];
    const float* Ar  = (const float*)d_in[2];
    const float* Ai  = (const float*)d_in[3];
    const float* Br  = (const float*)d_in[4];
    const float* Bi  = (const float*)d_in[5];
    const float* z0r = (const float*)d_in[6];
    const float* z0i = (const float*)d_in[7];
    float2* out = (float2*)d_out;

    pack_kernel<<<(OV * BSZ * UDIM) / 256, 256>>>(Ar, Ai, Br, Bi, z0r, z0i);
    wgemm_kernel<<<dim3(UDIM / 64, (BSZ * TLEN) / 128), 256>>>(xr, xi);
    scan_kernel<<<NCTA_SCAN, 128>>>(out);
}